// round 4
// baseline (speedup 1.0000x reference)
#include <cuda_runtime.h>
#include <math.h>

#define BB   16
#define NBB  512
#define KK   32
#define NBLK (BB * NBB)   /* 8192 (b, nb) blocks */
#define GW   0.3f

/* ---- scratch: per-block statistics (device globals; no allocation) ---- */
__device__ float2 g_vp  [NBLK];   /* (cnt_vld, sum_vld_p) */
__device__ float4 g_uncs[NBLK];   /* (sum_unc_p, sum_unc_p2, cnt_unc, 0) */
__device__ float2 g_bce [NBLK];   /* (bce_sum, bce_cnt) */
__device__ float2 g_sqqu[NBLK];   /* (sq, qu) */
__device__ unsigned int g_ctr = 0;

__device__ __forceinline__ float warp_sum(float v) {
    #pragma unroll
    for (int o = 16; o > 0; o >>= 1) v += __shfl_down_sync(0xFFFFFFFFu, v, o);
    return v;
}

/* ============ Pass 1: per-block stats + BCE partials (1 warp / block) ============ */
__global__ void __launch_bounds__(256) pass1_kernel(
    const float4* __restrict__ logits,
    const float4* __restrict__ targets,
    const int4*   __restrict__ sup_mask,
    const int4*   __restrict__ ign_mask)
{
    const int lane = threadIdx.x & 31;
    const int wid  = threadIdx.x >> 5;
    const int blk  = blockIdx.x * 8 + wid;       // (b*NBB + nb), grid = 1024
    const int v    = blk * 32 + lane;            // float4 index: 128 elems / 4

    const float4 x4 = logits[v];
    const float4 t4 = targets[v];
    const int4   s4 = sup_mask[v];
    const int4   i4 = ign_mask[v];

    float sum_vld_p = 0.f, sum_unc_p = 0.f, sum_unc_p2 = 0.f, bce = 0.f, cnts = 0.f;

    const float xs[4] = {x4.x, x4.y, x4.z, x4.w};
    const float ts[4] = {t4.x, t4.y, t4.z, t4.w};
    const int   ss[4] = {s4.x, s4.y, s4.z, s4.w};
    const int   is_[4]= {i4.x, i4.y, i4.z, i4.w};

    #pragma unroll
    for (int j = 0; j < 4; ++j) {
        const float x = xs[j];
        const bool  su = ss[j] != 0;
        const bool  ig = is_[j] != 0;
        const bool  vld = !ig;
        const bool  unc = vld && !su;

        const float p = 1.0f / (1.0f + __expf(-x));
        if (vld) { sum_vld_p += p; }
        if (unc) { sum_unc_p += p; sum_unc_p2 += p * p; }
        if (su)  { bce += fmaxf(x, 0.0f) - x * ts[j] + __logf(1.0f + __expf(-fabsf(x))); }
        /* pack counts: vld + 256*unc + 65536*sup  (sum < 2^24, exact in fp32) */
        cnts += (vld ? 1.0f : 0.0f) + (unc ? 256.0f : 0.0f) + (su ? 65536.0f : 0.0f);
    }

    sum_vld_p  = warp_sum(sum_vld_p);
    sum_unc_p  = warp_sum(sum_unc_p);
    sum_unc_p2 = warp_sum(sum_unc_p2);
    bce        = warp_sum(bce);
    cnts       = warp_sum(cnts);

    if (lane == 0) {
        const int ci = (int)cnts;
        g_vp  [blk] = make_float2((float)(ci & 255), sum_vld_p);
        g_uncs[blk] = make_float4(sum_unc_p, sum_unc_p2, (float)((ci >> 8) & 255), 0.0f);
        g_bce [blk] = make_float2(bce, (float)(ci >> 16));
    }
}

/* ===== Pass 2 (+ fused final reduction): gather K neighbor block-sums ===== */
__global__ void __launch_bounds__(256) pass2_kernel(
    const int* __restrict__ kv_indices,     // [B, NB, K]
    const int* __restrict__ kv_num_blocks,  // [B, NB]
    float* __restrict__ out)
{
    const int lane = threadIdx.x & 31;
    const int wid  = threadIdx.x >> 5;
    const int gid  = blockIdx.x * 8 + wid;       // b*NBB + qb, grid = 1024
    const int b    = gid >> 9;                   // /NBB

    /* independent loads — all issued up front, no serial chain */
    const int   idx  = kv_indices[gid * KK + lane];        // coalesced 128B
    const int   knb  = kv_num_blocks[gid];                 // warp-broadcast
    float2 vp        = g_vp[(b << 9) + idx];               // unconditional gather (idx in [0,512))
    float4 uncs;
    if (lane == 0) uncs = g_uncs[gid];

    if (lane >= knb) { vp.x = 0.0f; vp.y = 0.0f; }         // slot_ok & masking
    const float cv = warp_sum(vp.x);
    const float sp = warp_sum(vp.y);

    if (lane == 0) {
        const float nmean = sp / fmaxf(cv, 1.0f);
        const float qunc  = uncs.z;
        const bool  ok    = (qunc > 0.0f) && (knb > 0) && (cv > 0.0f);
        const float sq = uncs.y - 2.0f * nmean * uncs.x + nmean * nmean * qunc;
        g_sqqu[gid] = make_float2(ok ? sq : 0.0f, ok ? qunc : 0.0f);
    }

    /* ---- last-CTA final reduction (no per-thread threadfence) ---- */
    __shared__ bool is_last;
    __syncthreads();                 /* cta-scope release of lane-0 stores to thread 0 */
    if (threadIdx.x == 0) {
        unsigned int old;
        asm volatile("atom.acq_rel.gpu.add.u32 %0, [%1], %2;"
                     : "=r"(old) : "l"(&g_ctr), "r"(1u) : "memory");
        is_last = (old == gridDim.x - 1);
    }
    __syncthreads();
    if (!is_last) return;

    /* BCE sums: strided over 8192 packed partials */
    float bs = 0.0f, bc = 0.0f;
    for (int i = threadIdx.x; i < NBLK; i += 256) {
        const float2 p = g_bce[i];
        bs += p.x; bc += p.y;
    }
    bs = warp_sum(bs);
    bc = warp_sum(bc);

    __shared__ float shs[8], shc[8], bsq[BB], bqu[BB];
    if (lane == 0) { shs[wid] = bs; shc[wid] = bc; }

    /* graph: warp w handles batches 2w, 2w+1 */
    #pragma unroll
    for (int t = 0; t < 2; ++t) {
        const int bb = wid * 2 + t;
        float sq = 0.0f, qu = 0.0f;
        for (int i = lane; i < NBB; i += 32) {
            const float2 p = g_sqqu[bb * NBB + i];
            sq += p.x; qu += p.y;
        }
        sq = warp_sum(sq);
        qu = warp_sum(qu);
        if (lane == 0) { bsq[bb] = sq; bqu[bb] = qu; }
    }
    __syncthreads();

    if (threadIdx.x == 0) {
        float a = 0.0f, c = 0.0f;
        #pragma unroll
        for (int w = 0; w < 8; ++w) { a += shs[w]; c += shc[w]; }
        const float bce = a / fmaxf(c, 1.0f);

        float acc = 0.0f, nv = 0.0f;
        #pragma unroll
        for (int b2 = 0; b2 < BB; ++b2) {
            if (bqu[b2] > 0.0f) {
                acc += bsq[b2] / fmaxf(bqu[b2], 1.0f);
                nv  += 1.0f;
            }
        }
        out[0] = bce + GW * (acc / fmaxf(nv, 1.0f));
        g_ctr = 0;   /* self-reset for next graph replay */
    }
}

extern "C" void kernel_launch(void* const* d_in, const int* in_sizes, int n_in,
                              void* d_out, int out_size)
{
    const float4* logits        = (const float4*)d_in[0];
    const float4* targets       = (const float4*)d_in[1];
    const int4*   sup_mask      = (const int4*)d_in[2];
    const int4*   ign_mask      = (const int4*)d_in[3];
    const int*    kv_indices    = (const int*)d_in[4];
    const int*    kv_num_blocks = (const int*)d_in[5];
    float* out = (float*)d_out;

    pass1_kernel<<<NBLK / 8, 256>>>(logits, targets, sup_mask, ign_mask);
    pass2_kernel<<<NBLK / 8, 256>>>(kv_indices, kv_num_blocks, out);
}

// round 5
// speedup vs baseline: 1.2664x; 1.2664x over previous
#include <cuda_runtime.h>
#include <math.h>

#define BB    16
#define NBB   512
#define KK    32
#define NBLK  (BB * NBB)      /* 8192 (b, nb) blocks */
#define GW    0.3f
#define GRID  592             /* 4 CTAs/SM * 148 SMs -> all co-resident */
#define TPB   256
#define NWRP  (GRID * 8)      /* 4736 resident warps */

/* ---- scratch (device globals; no allocation) ---- */
__device__ float2 g_vp  [NBLK];   /* (cnt_vld, sum_vld_p) */
__device__ float4 g_uncs[NBLK];   /* (sum_unc_p, sum_unc_p2, cnt_unc, 0) */
__device__ float2 g_bce [NBLK];   /* (bce_sum, bce_cnt) */
__device__ float2 g_sqqu[NBLK];   /* (sq, qu) */
__device__ unsigned int g_bar1 = 0;
__device__ unsigned int g_done = 0;

__device__ __forceinline__ float warp_sum(float v) {
    #pragma unroll
    for (int o = 16; o > 0; o >>= 1) v += __shfl_down_sync(0xFFFFFFFFu, v, o);
    return v;
}

__device__ __forceinline__ unsigned int arrive_acq_rel(unsigned int* ctr) {
    unsigned int old;
    asm volatile("atom.acq_rel.gpu.add.u32 %0, [%1], 1;"
                 : "=r"(old) : "l"(ctr) : "memory");
    return old;
}

__global__ void __launch_bounds__(TPB, 4) fused_kernel(
    const float4* __restrict__ logits,
    const float4* __restrict__ targets,
    const int4*   __restrict__ sup_mask,
    const int4*   __restrict__ ign_mask,
    const int*    __restrict__ kv_indices,
    const int*    __restrict__ kv_num_blocks,
    float*        __restrict__ out)
{
    const int lane  = threadIdx.x & 31;
    const int wid   = threadIdx.x >> 5;
    const int gwarp = blockIdx.x * 8 + wid;

    /* ================= Phase A: per-block stats (1 warp / 128-elem block) ====== */
    for (int blk = gwarp; blk < NBLK; blk += NWRP) {
        const int v = blk * 32 + lane;          // float4 index (128 elems / 4)
        const float4 x4 = logits[v];
        const float4 t4 = targets[v];
        const int4   s4 = sup_mask[v];
        const int4   i4 = ign_mask[v];

        float sum_vld_p = 0.f, sum_unc_p = 0.f, sum_unc_p2 = 0.f, bce = 0.f, cnts = 0.f;
        const float xs[4] = {x4.x, x4.y, x4.z, x4.w};
        const float ts[4] = {t4.x, t4.y, t4.z, t4.w};
        const int   ss[4] = {s4.x, s4.y, s4.z, s4.w};
        const int   is_[4]= {i4.x, i4.y, i4.z, i4.w};

        #pragma unroll
        for (int j = 0; j < 4; ++j) {
            const float x  = xs[j];
            const bool  su = ss[j] != 0;
            const bool  ig = is_[j] != 0;
            const bool  vld = !ig;
            const bool  unc = vld && !su;

            const float p = 1.0f / (1.0f + __expf(-x));
            if (vld) sum_vld_p += p;
            if (unc) { sum_unc_p += p; sum_unc_p2 += p * p; }
            if (su)  bce += fmaxf(x, 0.0f) - x * ts[j] + __logf(1.0f + __expf(-fabsf(x)));
            /* pack counts: vld + 256*unc + 65536*sup (sum < 2^24, exact) */
            cnts += (vld ? 1.0f : 0.0f) + (unc ? 256.0f : 0.0f) + (su ? 65536.0f : 0.0f);
        }

        sum_vld_p  = warp_sum(sum_vld_p);
        sum_unc_p  = warp_sum(sum_unc_p);
        sum_unc_p2 = warp_sum(sum_unc_p2);
        bce        = warp_sum(bce);
        cnts       = warp_sum(cnts);

        if (lane == 0) {
            const int ci = (int)cnts;
            g_vp  [blk] = make_float2((float)(ci & 255), sum_vld_p);
            g_uncs[blk] = make_float4(sum_unc_p, sum_unc_p2, (float)((ci >> 8) & 255), 0.0f);
            g_bce [blk] = make_float2(bce, (float)(ci >> 16));
        }
    }

    /* ================= grid barrier (all 592 CTAs resident -> safe spin) ======= */
    __syncthreads();
    if (threadIdx.x == 0) {
        const unsigned int old = arrive_acq_rel(&g_bar1);
        if (old != GRID - 1) {
            unsigned int v;
            do {
                asm volatile("ld.acquire.gpu.u32 %0, [%1];"
                             : "=r"(v) : "l"(&g_bar1) : "memory");
            } while (v < GRID);
        }
    }
    __syncthreads();

    /* ================= Phase B: gather K neighbor block-sums (1 warp / q-block) */
    for (int gid = gwarp; gid < NBLK; gid += NWRP) {
        const int b   = gid >> 9;
        const int idx = kv_indices[gid * KK + lane];   // coalesced 128B
        const int knb = kv_num_blocks[gid];            // warp-broadcast
        float2 vp     = g_vp[(b << 9) + idx];          // idx always in [0,512)
        float4 uncs;
        if (lane == 0) uncs = g_uncs[gid];

        if (lane >= knb) { vp.x = 0.0f; vp.y = 0.0f; }
        const float cv = warp_sum(vp.x);
        const float sp = warp_sum(vp.y);

        if (lane == 0) {
            const float nmean = sp / fmaxf(cv, 1.0f);
            const float qunc  = uncs.z;
            const bool  ok    = (qunc > 0.0f) && (knb > 0) && (cv > 0.0f);
            const float sq = uncs.y - 2.0f * nmean * uncs.x + nmean * nmean * qunc;
            g_sqqu[gid] = make_float2(ok ? sq : 0.0f, ok ? qunc : 0.0f);
        }
    }

    /* ================= last-CTA final reduction (fixed order, deterministic) == */
    __shared__ bool is_last;
    __syncthreads();
    if (threadIdx.x == 0) {
        const unsigned int old = arrive_acq_rel(&g_done);
        is_last = (old == GRID - 1);
    }
    __syncthreads();
    if (!is_last) return;

    float bs = 0.0f, bc = 0.0f;
    for (int i = threadIdx.x; i < NBLK; i += TPB) {
        const float2 p = g_bce[i];
        bs += p.x; bc += p.y;
    }
    bs = warp_sum(bs);
    bc = warp_sum(bc);

    __shared__ float shs[8], shc[8], bsq[BB], bqu[BB];
    if (lane == 0) { shs[wid] = bs; shc[wid] = bc; }

    #pragma unroll
    for (int t = 0; t < 2; ++t) {
        const int bb = wid * 2 + t;
        float sq = 0.0f, qu = 0.0f;
        for (int i = lane; i < NBB; i += 32) {
            const float2 p = g_sqqu[bb * NBB + i];
            sq += p.x; qu += p.y;
        }
        sq = warp_sum(sq);
        qu = warp_sum(qu);
        if (lane == 0) { bsq[bb] = sq; bqu[bb] = qu; }
    }
    __syncthreads();

    if (threadIdx.x == 0) {
        float a = 0.0f, c = 0.0f;
        #pragma unroll
        for (int w = 0; w < 8; ++w) { a += shs[w]; c += shc[w]; }
        const float bce = a / fmaxf(c, 1.0f);

        float acc = 0.0f, nv = 0.0f;
        #pragma unroll
        for (int b2 = 0; b2 < BB; ++b2) {
            if (bqu[b2] > 0.0f) {
                acc += bsq[b2] / fmaxf(bqu[b2], 1.0f);
                nv  += 1.0f;
            }
        }
        out[0] = bce + GW * (acc / fmaxf(nv, 1.0f));
        /* self-reset for next graph replay: every CTA already arrived at both
           counters and nothing reads them after this point. */
        g_bar1 = 0;
        g_done = 0;
    }
}

extern "C" void kernel_launch(void* const* d_in, const int* in_sizes, int n_in,
                              void* d_out, int out_size)
{
    const float4* logits        = (const float4*)d_in[0];
    const float4* targets       = (const float4*)d_in[1];
    const int4*   sup_mask      = (const int4*)d_in[2];
    const int4*   ign_mask      = (const int4*)d_in[3];
    const int*    kv_indices    = (const int*)d_in[4];
    const int*    kv_num_blocks = (const int*)d_in[5];
    float* out = (float*)d_out;

    fused_kernel<<<GRID, TPB>>>(logits, targets, sup_mask, ign_mask,
                                kv_indices, kv_num_blocks, out);
}

// round 6
// speedup vs baseline: 1.4138x; 1.1164x over previous
#include <cuda_runtime.h>
#include <math.h>

#define BB    16
#define NBB   512
#define KK    32
#define NBLK  (BB * NBB)      /* 8192 (b, nb) blocks */
#define GW    0.3f
#define GRID  512             /* 4 CTAs/SM guaranteed resident (<=64 regs) */
#define TPB   256

/* ---- scratch (device globals; no allocation) ---- */
__device__ float2 g_vp     [NBLK];  /* (cnt_vld, sum_vld_p) */
__device__ float4 g_uncs   [NBLK];  /* (sum_unc_p, sum_unc_p2, cnt_unc, 0) */
__device__ float2 g_cta_bce[GRID];  /* per-CTA (bce_sum, bce_cnt) */
__device__ float2 g_cta_sq [GRID];  /* per-CTA (sq, qu) — one batch per CTA */
__device__ unsigned int g_bar1 = 0;
__device__ unsigned int g_done = 0;

__device__ __forceinline__ float warp_sum(float v) {
    #pragma unroll
    for (int o = 16; o > 0; o >>= 1) v += __shfl_down_sync(0xFFFFFFFFu, v, o);
    return v;
}

__device__ __forceinline__ unsigned int arrive_acq_rel(unsigned int* ctr) {
    unsigned int old;
    asm volatile("atom.acq_rel.gpu.add.u32 %0, [%1], 1;"
                 : "=r"(old) : "l"(ctr) : "memory");
    return old;
}

struct Stats { float svp, sup_, sup2, bce, cnts; };

__device__ __forceinline__ Stats block_stats(const float4& x4, const float4& t4,
                                             const int4& s4, const int4& i4) {
    Stats r = {0.f, 0.f, 0.f, 0.f, 0.f};
    const float xs[4] = {x4.x, x4.y, x4.z, x4.w};
    const float ts[4] = {t4.x, t4.y, t4.z, t4.w};
    const int   ss[4] = {s4.x, s4.y, s4.z, s4.w};
    const int   is_[4]= {i4.x, i4.y, i4.z, i4.w};
    #pragma unroll
    for (int j = 0; j < 4; ++j) {
        const float x  = xs[j];
        const bool  su = ss[j] != 0;
        const bool  ig = is_[j] != 0;
        const bool  vld = !ig;
        const bool  unc = vld && !su;
        const float p = 1.0f / (1.0f + __expf(-x));
        if (vld) r.svp += p;
        if (unc) { r.sup_ += p; r.sup2 += p * p; }
        if (su)  r.bce += fmaxf(x, 0.0f) - x * ts[j] + __logf(1.0f + __expf(-fabsf(x)));
        /* pack counts: vld + 256*unc + 65536*sup (sum < 2^24, exact) */
        r.cnts += (vld ? 1.0f : 0.0f) + (unc ? 256.0f : 0.0f) + (su ? 65536.0f : 0.0f);
    }
    return r;
}

__global__ void __launch_bounds__(TPB, 4) fused_kernel(
    const float4* __restrict__ logits,
    const float4* __restrict__ targets,
    const int4*   __restrict__ sup_mask,
    const int4*   __restrict__ ign_mask,
    const int*    __restrict__ kv_indices,
    const int*    __restrict__ kv_num_blocks,
    float*        __restrict__ out)
{
    const int lane  = threadIdx.x & 31;
    const int wid   = threadIdx.x >> 5;
    const int gwarp = blockIdx.x * 8 + wid;      /* 0..4095, owns blocks 2w,2w+1 */

    __shared__ float2 sh_bce[8];
    __shared__ float2 sh_sq[16];
    __shared__ float  bsq[BB], bqu[BB];
    __shared__ float  s_bce;
    __shared__ bool   is_last;

    /* ============ Phase A: 2 blocks per warp, fully unrolled (MLP=8) ========== */
    {
        const int blk0 = gwarp * 2;
        const int v0   = blk0 * 32 + lane;
        const int v1   = v0 + 32;

        const float4 xa = logits[v0],   xb = logits[v1];
        const float4 ta = targets[v0],  tb = targets[v1];
        const int4   sa = sup_mask[v0], sb = sup_mask[v1];
        const int4   ia = ign_mask[v0], ib = ign_mask[v1];

        Stats A = block_stats(xa, ta, sa, ia);
        Stats B = block_stats(xb, tb, sb, ib);

        /* ten independent shuffle trees — latencies overlap */
        A.svp  = warp_sum(A.svp);   B.svp  = warp_sum(B.svp);
        A.sup_ = warp_sum(A.sup_);  B.sup_ = warp_sum(B.sup_);
        A.sup2 = warp_sum(A.sup2);  B.sup2 = warp_sum(B.sup2);
        A.bce  = warp_sum(A.bce);   B.bce  = warp_sum(B.bce);
        A.cnts = warp_sum(A.cnts);  B.cnts = warp_sum(B.cnts);

        if (lane == 0) {
            const int ca = (int)A.cnts, cb = (int)B.cnts;
            g_vp  [blk0]     = make_float2((float)(ca & 255), A.svp);
            g_vp  [blk0 + 1] = make_float2((float)(cb & 255), B.svp);
            g_uncs[blk0]     = make_float4(A.sup_, A.sup2, (float)((ca >> 8) & 255), 0.f);
            g_uncs[blk0 + 1] = make_float4(B.sup_, B.sup2, (float)((cb >> 8) & 255), 0.f);
            sh_bce[wid] = make_float2(A.bce + B.bce, (float)((ca >> 16) + (cb >> 16)));
        }
    }
    __syncthreads();
    if (threadIdx.x == 0) {
        float s = 0.f, c = 0.f;
        #pragma unroll
        for (int w = 0; w < 8; ++w) { s += sh_bce[w].x; c += sh_bce[w].y; }
        g_cta_bce[blockIdx.x] = make_float2(s, c);
        /* grid barrier arrive (release orders all prior CTA stores) */
        const unsigned int old = arrive_acq_rel(&g_bar1);
        if (old != GRID - 1) {
            unsigned int v;
            do {
                asm volatile("ld.acquire.gpu.u32 %0, [%1];"
                             : "=r"(v) : "l"(&g_bar1) : "memory");
            } while (v < GRID);
        }
    }
    __syncthreads();

    /* ============ Phase B: 2 query blocks per warp, unrolled ================= */
    {
        const int gid0 = gwarp * 2, gid1 = gid0 + 1;
        const int base = (gid0 >> 9) << 9;            /* same batch for both */

        const int idx0 = kv_indices[gid0 * KK + lane];
        const int idx1 = kv_indices[gid1 * KK + lane];
        const int knb0 = kv_num_blocks[gid0];
        const int knb1 = kv_num_blocks[gid1];
        float2 vp0 = g_vp[base + idx0];
        float2 vp1 = g_vp[base + idx1];
        float4 u0, u1;
        if (lane == 0) { u0 = g_uncs[gid0]; u1 = g_uncs[gid1]; }

        if (lane >= knb0) { vp0.x = 0.f; vp0.y = 0.f; }
        if (lane >= knb1) { vp1.x = 0.f; vp1.y = 0.f; }
        const float cv0 = warp_sum(vp0.x), sp0 = warp_sum(vp0.y);
        const float cv1 = warp_sum(vp1.x), sp1 = warp_sum(vp1.y);

        if (lane == 0) {
            const float nm0 = sp0 / fmaxf(cv0, 1.0f);
            const float nm1 = sp1 / fmaxf(cv1, 1.0f);
            const bool ok0 = (u0.z > 0.f) && (knb0 > 0) && (cv0 > 0.f);
            const bool ok1 = (u1.z > 0.f) && (knb1 > 0) && (cv1 > 0.f);
            const float sq0 = u0.y - 2.0f * nm0 * u0.x + nm0 * nm0 * u0.z;
            const float sq1 = u1.y - 2.0f * nm1 * u1.x + nm1 * nm1 * u1.z;
            sh_sq[wid * 2]     = make_float2(ok0 ? sq0 : 0.f, ok0 ? u0.z : 0.f);
            sh_sq[wid * 2 + 1] = make_float2(ok1 ? sq1 : 0.f, ok1 ? u1.z : 0.f);
        }
    }
    __syncthreads();
    if (threadIdx.x == 0) {
        float s = 0.f, q = 0.f;
        #pragma unroll
        for (int i = 0; i < 16; ++i) { s += sh_sq[i].x; q += sh_sq[i].y; }
        g_cta_sq[blockIdx.x] = make_float2(s, q);     /* whole CTA = one batch */
        const unsigned int old = arrive_acq_rel(&g_done);
        is_last = (old == GRID - 1);
    }
    __syncthreads();
    if (!is_last) return;

    /* ============ Phase C: last CTA, 8 KB of partials, fixed order =========== */
    if (wid == 0) {
        float bs = 0.f, bc = 0.f;
        #pragma unroll
        for (int i = 0; i < GRID / 32; ++i) {         /* 16 iterations */
            const float2 p = g_cta_bce[lane + 32 * i];
            bs += p.x; bc += p.y;
        }
        bs = warp_sum(bs);
        bc = warp_sum(bc);
        if (lane == 0) s_bce = bs / fmaxf(bc, 1.0f);
    }

    #pragma unroll
    for (int t = 0; t < 2; ++t) {                     /* warp w -> batches 2w,2w+1 */
        const int bb = wid * 2 + t;
        const float2 p = g_cta_sq[bb * 32 + lane];    /* 32 CTAs per batch */
        const float sq = warp_sum(p.x);
        const float qu = warp_sum(p.y);
        if (lane == 0) { bsq[bb] = sq; bqu[bb] = qu; }
    }
    __syncthreads();

    if (threadIdx.x == 0) {
        float acc = 0.f, nv = 0.f;
        #pragma unroll
        for (int b2 = 0; b2 < BB; ++b2) {
            if (bqu[b2] > 0.0f) {
                acc += bsq[b2] / fmaxf(bqu[b2], 1.0f);
                nv  += 1.0f;
            }
        }
        out[0] = s_bce + GW * (acc / fmaxf(nv, 1.0f));
        g_bar1 = 0;   /* safe: every CTA already passed both counters */
        g_done = 0;
    }
}

extern "C" void kernel_launch(void* const* d_in, const int* in_sizes, int n_in,
                              void* d_out, int out_size)
{
    const float4* logits        = (const float4*)d_in[0];
    const float4* targets       = (const float4*)d_in[1];
    const int4*   sup_mask      = (const int4*)d_in[2];
    const int4*   ign_mask      = (const int4*)d_in[3];
    const int*    kv_indices    = (const int*)d_in[4];
    const int*    kv_num_blocks = (const int*)d_in[5];
    float* out = (float*)d_out;

    fused_kernel<<<GRID, TPB>>>(logits, targets, sup_mask, ign_mask,
                                kv_indices, kv_num_blocks, out);
}